// round 17
// baseline (speedup 1.0000x reference)
#include <cuda_runtime.h>
#include <cuda_fp16.h>
#include <cuda_bf16.h>

#define N_NODES 100000
#define MAX_NNZ 3200000
#define ELL_CAP 128   // slots/row; Poisson(32) => P(deg>=128) ~ e^-88, never hit

// Exact power-of-2 scaling for post-W2 stages (keeps t' in fp16-normal range)
#define GSCALE     1024.0f
#define GSCALE_INV (1.0f / 1024.0f)

// ---------------- scratch (no cudaMalloc allowed) ----------------
__device__ __half g_xh [(size_t)N_NODES * 128];
__device__ __half g_ha [(size_t)N_NODES * 128];
__device__ __half g_hb [(size_t)N_NODES * 128];
__device__ __half g_w1h[256 * 128];
__device__ __half g_w2h[128 * 256];
__device__ int    g_cnt[N_NODES];
__device__ unsigned long long g_ell[(size_t)N_NODES * ELL_CAP]; // (col lo, val bits hi)

// ---------------------------------------------------------------------------
// Prep: ELL scatter + fp32->fp16 converts (vectorized, float2 -> half2).
// ---------------------------------------------------------------------------
__global__ void prep_kernel(const int* __restrict__ rows,
                            const int* __restrict__ cols,
                            const float* __restrict__ vals, int nnz,
                            const float* __restrict__ x,  int p0,   // pairs
                            const float* __restrict__ w1, int p1,
                            const float* __restrict__ w2, int p2) {
    int i = blockIdx.x * blockDim.x + threadIdx.x;
    if (i < nnz) {
        int r = rows[i];
        int pos = atomicAdd(&g_cnt[r], 1);
        if (pos < ELL_CAP) {
            unsigned vbits = __float_as_uint(vals[i]);
            g_ell[(size_t)r * ELL_CAP + pos] =
                (unsigned long long)(unsigned)cols[i]
              | ((unsigned long long)vbits << 32);
        }
        return;
    }
    i -= nnz;
    if (i < p0) {
        float2 f = reinterpret_cast<const float2*>(x)[i];
        reinterpret_cast<__half2*>(g_xh)[i] = __floats2half2_rn(f.x, f.y);
        return;
    }
    i -= p0;
    if (i < p1) {
        float2 f = reinterpret_cast<const float2*>(w1)[i];
        reinterpret_cast<__half2*>(g_w1h)[i] = __floats2half2_rn(f.x, f.y);
        return;
    }
    i -= p1;
    if (i < p2) {
        float2 f = reinterpret_cast<const float2*>(w2)[i];
        reinterpret_cast<__half2*>(g_w2h)[i] = __floats2half2_rn(f.x, f.y);
    }
}

// ---------------------------------------------------------------------------
// Gather SpMM (d=128): one warp per row, lane owns 4 features, fp32 accum.
// Edge stream read 2-at-a-time via 16B loads (ELL rows are 1024B-aligned).
// ---------------------------------------------------------------------------
__device__ __forceinline__ void acc_gather(const __half* __restrict__ h,
                                           int c, float v, int lane, float4& acc) {
    uint2 u = __ldg(reinterpret_cast<const uint2*>(h + (size_t)c * 128) + lane);
    __half2 p0 = *reinterpret_cast<__half2*>(&u.x);
    __half2 p1 = *reinterpret_cast<__half2*>(&u.y);
    float2 f0 = __half22float2(p0);
    float2 f1 = __half22float2(p1);
    acc.x = fmaf(v, f0.x, acc.x); acc.y = fmaf(v, f0.y, acc.y);
    acc.z = fmaf(v, f1.x, acc.z); acc.w = fmaf(v, f1.y, acc.w);
}

template <bool OUT_HALF>
__global__ void __launch_bounds__(256)
spmm_ell_kernel(const __half* __restrict__ h, void* __restrict__ outv, float oscale) {
    int r = (blockIdx.x * blockDim.x + threadIdx.x) >> 5;
    if (r >= N_NODES) return;
    int lane = threadIdx.x & 31;

    int cnt = __ldg(&g_cnt[r]);
    if (cnt > ELL_CAP) cnt = ELL_CAP;
    const unsigned long long* ebase = g_ell + (size_t)r * ELL_CAP;

    float4 acc = make_float4(0.f, 0.f, 0.f, 0.f);
    int e = 0;
    for (; e + 3 < cnt; e += 4) {
        // two 16B loads = 4 edges (ebase is 1024B-aligned, e % 4 == 0 here)
        uint4 q0 = __ldg(reinterpret_cast<const uint4*>(ebase + e));
        uint4 q1 = __ldg(reinterpret_cast<const uint4*>(ebase + e + 2));
        acc_gather(h, (int)q0.x, __uint_as_float(q0.y), lane, acc);
        acc_gather(h, (int)q0.z, __uint_as_float(q0.w), lane, acc);
        acc_gather(h, (int)q1.x, __uint_as_float(q1.y), lane, acc);
        acc_gather(h, (int)q1.z, __uint_as_float(q1.w), lane, acc);
    }
    for (; e < cnt; e++) {
        uint2 p = __ldg(reinterpret_cast<const uint2*>(ebase + e));
        acc_gather(h, (int)p.x, __uint_as_float(p.y), lane, acc);
    }

    acc.x *= oscale; acc.y *= oscale; acc.z *= oscale; acc.w *= oscale;

    if (OUT_HALF) {
        __half2 o0 = __floats2half2_rn(acc.x, acc.y);
        __half2 o1 = __floats2half2_rn(acc.z, acc.w);
        uint2 u;
        u.x = *reinterpret_cast<unsigned*>(&o0);
        u.y = *reinterpret_cast<unsigned*>(&o1);
        *(reinterpret_cast<uint2*>((__half*)outv + (size_t)r * 128) + lane) = u;
    } else {
        *(reinterpret_cast<float4*>((float*)outv + (size_t)r * 128) + lane) = acc;
    }
}

// ---------------------------------------------------------------------------
// asm helpers
// ---------------------------------------------------------------------------
__device__ __forceinline__ void ldsm_x4(unsigned* d, unsigned addr) {
    asm volatile("ldmatrix.sync.aligned.m8n8.x4.shared.b16 {%0,%1,%2,%3}, [%4];"
                 : "=r"(d[0]), "=r"(d[1]), "=r"(d[2]), "=r"(d[3]) : "r"(addr));
}
__device__ __forceinline__ void cp16(unsigned dst, const void* src) {
    asm volatile("cp.async.cg.shared.global [%0], [%1], 16;" :: "r"(dst), "l"(src));
}
__device__ __forceinline__ void cp_commit() {
    asm volatile("cp.async.commit_group;");
}
template <int NG>
__device__ __forceinline__ void cp_wait() {
    asm volatile("cp.async.wait_group %0;" :: "n"(NG));
}
__device__ __forceinline__ void mma16816(float* c, const unsigned* a, unsigned b0, unsigned b1) {
    asm volatile(
        "mma.sync.aligned.m16n8k16.row.col.f32.f16.f16.f32 "
        "{%0,%1,%2,%3}, {%4,%5,%6,%7}, {%8,%9}, {%0,%1,%2,%3};\n"
        : "+f"(c[0]), "+f"(c[1]), "+f"(c[2]), "+f"(c[3])
        : "r"(a[0]), "r"(a[1]), "r"(a[2]), "r"(a[3]), "r"(b0), "r"(b1));
}

// ---------------------------------------------------------------------------
// Fused MLP, fully-resident weights: C = GSCALE*(relu(A@W1^T)@W2^T), [N,128].
// W1 (256x128) + W2 (128x256) + A-tile all live in smem (172 KB, 1 CTA/SM):
// ONE barrier total; each warp then runs its whole 512-mma stream with no
// inter-warp sync. A-fragments hoisted to registers (chunk-invariant).
// Register fusion as in R12: warp owns 16 rows, GEMM2 A-frags are an
// in-register relu+pack of GEMM1 accumulators.
// LDSA=136h, LDSW2=264h: row strides == 4 banks mod 32 -> ldsm conflict-free.
// ---------------------------------------------------------------------------
#define LDSA  136
#define LDSW2 264
#define SM_AS  0                          // 128 x LDSA
#define SM_W1F (128 * LDSA)               // 256 x LDSA
#define SM_W2F (SM_W1F + 256 * LDSA)      // 128 x LDSW2
#define SM_TOTAL (SM_W2F + 128 * LDSW2)   // 86,016 halves = 172,032 B

__global__ void __launch_bounds__(256, 1)
fused_mlp_kernel(const __half* __restrict__ A,
                 const __half* __restrict__ W1,
                 const __half* __restrict__ W2,
                 __half* __restrict__ C, int N) {
    extern __shared__ __half sm[];

    const int tid  = threadIdx.x;
    const int lane = tid & 31;
    const int wid  = tid >> 5;          // 0..7, warp owns rows wid*16..+16
    const int gid = lane >> 2;
    const int tig = lane & 3;
    const int rowBase = blockIdx.x * 128;

    // ldmatrix lane-address components (validated by R11/R12 passing runs):
    const int lane15 = lane & 15;
    const int laneK8 = (lane & 16) ? 8 : 0;
    const int laneJ  = ((lane & 16) ? 8 : 0) + (lane & 7);
    const int laneBK = (lane & 8) ? 8 : 0;

    const unsigned smBase = (unsigned)__cvta_generic_to_shared(sm);

    // ---- prologue: A tile + FULL W1 + FULL W2 via cp.async, one wait+barrier
    for (int i = tid; i < 128 * 16; i += 256) {
        int row = i >> 4, seg = (i & 15) * 8;
        unsigned dst = smBase + (unsigned)((SM_AS + row * LDSA + seg) * 2);
        int arow = rowBase + row;
        if (arow < N) {
            cp16(dst, A + (size_t)arow * 128 + seg);
        } else {
            *reinterpret_cast<uint4*>(sm + SM_AS + row * LDSA + seg) = make_uint4(0, 0, 0, 0);
        }
    }
    for (int i = tid; i < 256 * 16; i += 256) {
        int row = i >> 4, seg = (i & 15) * 8;
        cp16(smBase + (unsigned)((SM_W1F + row * LDSA + seg) * 2),
             W1 + (size_t)row * 128 + seg);
    }
    for (int i = tid; i < 128 * 32; i += 256) {
        int row = i >> 5, seg = (i & 31) * 8;
        cp16(smBase + (unsigned)((SM_W2F + row * LDSW2 + seg) * 2),
             W2 + (size_t)row * 256 + seg);
    }
    cp_commit();
    cp_wait<0>();
    __syncthreads();    // the ONLY barrier

    // ---- hoist A-fragments (chunk-invariant): a[k0/16][4]
    unsigned afrag[8][4];
    {
        const unsigned aBase = smBase +
            (unsigned)((SM_AS + (wid * 16 + lane15) * LDSA + laneK8) * 2);
#pragma unroll
        for (int k = 0; k < 8; k++)
            ldsm_x4(afrag[k], aBase + (unsigned)(k * 16 * 2));
    }

    float oacc[16][4];
#pragma unroll
    for (int n = 0; n < 16; n++)
#pragma unroll
        for (int q = 0; q < 4; q++) oacc[n][q] = 0.f;

    const unsigned w1LaneBase = smBase + (unsigned)((SM_W1F + laneJ * LDSA + laneBK) * 2);
    const unsigned w2LaneBase = smBase + (unsigned)((SM_W2F + laneJ * LDSW2 + laneBK) * 2);

#pragma unroll
    for (int kc = 0; kc < 4; kc++) {
        unsigned ah[4][4];   // GEMM2 A-fragments: ah[q] = chunk features q*16..+16

        // ---- GEMM1 in two 32-feature halves (keeps register peak low)
#pragma unroll
        for (int hh = 0; hh < 2; hh++) {
            float pacc[4][4];
#pragma unroll
            for (int n = 0; n < 4; n++)
#pragma unroll
                for (int q = 0; q < 4; q++) pacc[n][q] = 0.f;

#pragma unroll
            for (int k0 = 0; k0 < 128; k0 += 16) {
                unsigned b[4][2];
#pragma unroll
                for (int p = 0; p < 2; p++) {
                    unsigned d[4];
                    ldsm_x4(d, w1LaneBase +
                        (unsigned)(((kc * 64 + hh * 32 + p * 16) * LDSA + k0) * 2));
                    b[2 * p][0] = d[0]; b[2 * p][1] = d[1];
                    b[2 * p + 1][0] = d[2]; b[2 * p + 1][1] = d[3];
                }
#pragma unroll
                for (int n = 0; n < 4; n++)
                    mma16816(pacc[n], afrag[k0 >> 4], b[n][0], b[n][1]);
            }

            // relu + pack into GEMM2 A-fragments (pure register repack)
#pragma unroll
            for (int qq = 0; qq < 2; qq++) {
                int q = hh * 2 + qq;
                __half2 t0 = __floats2half2_rn(fmaxf(pacc[2 * qq][0], 0.f), fmaxf(pacc[2 * qq][1], 0.f));
                __half2 t1 = __floats2half2_rn(fmaxf(pacc[2 * qq][2], 0.f), fmaxf(pacc[2 * qq][3], 0.f));
                __half2 t2 = __floats2half2_rn(fmaxf(pacc[2 * qq + 1][0], 0.f), fmaxf(pacc[2 * qq + 1][1], 0.f));
                __half2 t3 = __floats2half2_rn(fmaxf(pacc[2 * qq + 1][2], 0.f), fmaxf(pacc[2 * qq + 1][3], 0.f));
                ah[q][0] = *reinterpret_cast<unsigned*>(&t0);
                ah[q][1] = *reinterpret_cast<unsigned*>(&t1);
                ah[q][2] = *reinterpret_cast<unsigned*>(&t2);
                ah[q][3] = *reinterpret_cast<unsigned*>(&t3);
            }
        }

        // ---- GEMM2: oacc += P @ W2[:, kc*64..+64]^T
#pragma unroll
        for (int q = 0; q < 4; q++) {
#pragma unroll
            for (int p = 0; p < 8; p++) {
                unsigned d[4];
                ldsm_x4(d, w2LaneBase +
                    (unsigned)((p * 16 * LDSW2 + kc * 64 + q * 16) * 2));
                mma16816(oacc[2 * p],     ah[q], d[0], d[1]);
                mma16816(oacc[2 * p + 1], ah[q], d[2], d[3]);
            }
        }
    }

    // ---- epilogue: C = GSCALE * oacc (fp16); oacc[n] -> cols n*8 + tig*2
    int r0 = rowBase + wid * 16 + gid;
    int r1 = r0 + 8;
#pragma unroll
    for (int n = 0; n < 16; n++) {
        int col = n * 8 + tig * 2;
        if (r0 < N) {
            __half2 p = __floats2half2_rn(oacc[n][0] * GSCALE, oacc[n][1] * GSCALE);
            *reinterpret_cast<__half2*>(C + (size_t)r0 * 128 + col) = p;
        }
        if (r1 < N) {
            __half2 p = __floats2half2_rn(oacc[n][2] * GSCALE, oacc[n][3] * GSCALE);
            *reinterpret_cast<__half2*>(C + (size_t)r1 * 128 + col) = p;
        }
    }
}

// ---------------------------------------------------------------------------
// Sequence:
//   memset cnt; prep (ELL scatter + vectorized fp16 converts)
//   h1 = A@xh; h2 = A@h1
//   g' = 1024*relu(h2@W1^T)@W2^T   (resident-weight register-fused MLP)
//   t' = A@g';  out = (A@t')/1024  (fp32)
// ---------------------------------------------------------------------------
extern "C" void kernel_launch(void* const* d_in, const int* in_sizes, int n_in,
                              void* d_out, int out_size) {
    const float* x    = (const float*)d_in[0];
    const int*   rows = (const int*)  d_in[1];
    const int*   cols = (const int*)  d_in[2];
    const float* vals = (const float*)d_in[3];
    const float* W1   = (const float*)d_in[4];
    const float* W2   = (const float*)d_in[5];
    float* out = (float*)d_out;

    const int nnz = in_sizes[1];
    const int N   = N_NODES;

    __half *xh, *ha, *hb, *w1h, *w2h;
    int *cnt;
    cudaGetSymbolAddress((void**)&xh,  g_xh);
    cudaGetSymbolAddress((void**)&ha,  g_ha);
    cudaGetSymbolAddress((void**)&hb,  g_hb);
    cudaGetSymbolAddress((void**)&w1h, g_w1h);
    cudaGetSymbolAddress((void**)&w2h, g_w2h);
    cudaGetSymbolAddress((void**)&cnt, g_cnt);

    const int BT = 256;
    const int spmmBlocks = (N * 32 + BT - 1) / BT;

    const int smemFused = SM_TOTAL * (int)sizeof(__half);   // 172,032 B
    cudaFuncSetAttribute(fused_mlp_kernel,
                         cudaFuncAttributeMaxDynamicSharedMemorySize, smemFused);

    // ---- ELL build + converts
    cudaMemsetAsync(cnt, 0, N * sizeof(int));
    {
        int p0 = N * 128 / 2, p1 = 256 * 128 / 2, p2 = 128 * 256 / 2;
        long long tot = (long long)nnz + p0 + p1 + p2;
        prep_kernel<<<(int)((tot + BT - 1) / BT), BT>>>(rows, cols, vals, nnz,
                                                        x, p0, W1, p1, W2, p2);
    }

    // ---- layer 1 propagates
    spmm_ell_kernel<true><<<spmmBlocks, BT>>>(xh, ha, 1.0f);   // h1
    spmm_ell_kernel<true><<<spmmBlocks, BT>>>(ha, hb, 1.0f);   // h2

    // ---- fused MLP: g' = 1024 * relu(h2@W1^T)@W2^T  -> ha
    fused_mlp_kernel<<<(N + 127) / 128, 256, smemFused>>>(hb, w1h, w2h, ha, N);

    // ---- layer 2 propagates
    spmm_ell_kernel<true ><<<spmmBlocks, BT>>>(ha, hb, 1.0f);        // t' = A@g'
    spmm_ell_kernel<false><<<spmmBlocks, BT>>>(hb, out, GSCALE_INV); // out = (A@t')/1024
}